// round 1
// baseline (speedup 1.0000x reference)
#include <cuda_runtime.h>
#include <math.h>

// Problem shape (fixed by the reference)
#define B_SZ 16384
#define C_SZ 4096
#define D_SZ 256
#define K_SZ 512   // packed K = 2*D

// -------- scratch (no allocation allowed -> __device__ globals) --------
__device__ float g_A[(size_t)B_SZ * K_SZ];      // [B, 512] : [z^2 | z]
__device__ float g_W[(size_t)C_SZ * K_SZ];      // [C, 512] : [inv_var | -2*mu*inv_var]
__device__ float g_constc[C_SZ];                // sum_d (mu^2*iv + logvar)

// ------------------------------ prep kernels ------------------------------
__global__ void prep_A_kernel(const float* __restrict__ z) {
    int idx = blockIdx.x * blockDim.x + threadIdx.x;
    if (idx >= B_SZ * D_SZ) return;
    int b = idx >> 8;          // / 256
    int d = idx & 255;         // % 256
    float v = z[idx];
    g_A[(size_t)b * K_SZ + d]        = v * v;
    g_A[(size_t)b * K_SZ + D_SZ + d] = v;
}

__global__ void prep_W_kernel(const float* __restrict__ mu,
                              const float* __restrict__ logvar) {
    // one block (256 threads) per class c
    int c = blockIdx.x;
    int d = threadIdx.x;
    float lv = logvar[(size_t)c * D_SZ + d];
    float m  = mu[(size_t)c * D_SZ + d];
    float iv = expf(-lv);
    g_W[(size_t)c * K_SZ + d]        = iv;
    g_W[(size_t)c * K_SZ + D_SZ + d] = -2.0f * m * iv;

    __shared__ float red[256];
    red[d] = m * m * iv + lv;
    __syncthreads();
    #pragma unroll
    for (int s = 128; s > 0; s >>= 1) {
        if (d < s) red[d] += red[d + s];
        __syncthreads();
    }
    if (d == 0) g_constc[c] = red[0];
}

// ------------------------------ main GEMM ------------------------------
// logits[b,c] = -0.5f * (A[b,:]·W[c,:] + constc[c]) + OFF
// OFF = -0.5*D*log(2*pi) + log(1/C)
#define BM 128
#define BN 128
#define BK 16
#define NKT (K_SZ / BK)   // 32

__global__ void __launch_bounds__(256, 2)
gemm_logits_kernel(float* __restrict__ out) {
    __shared__ float As[2][BK][BM];
    __shared__ float Ws[2][BK][BN];

    const int tid = threadIdx.x;
    const int m0 = blockIdx.y * BM;
    const int n0 = blockIdx.x * BN;
    const int ty = tid >> 4;    // 0..15 (row group)
    const int tx = tid & 15;    // 0..15 (col group)

    float acc[8][8];
    #pragma unroll
    for (int i = 0; i < 8; i++)
        #pragma unroll
        for (int j = 0; j < 8; j++) acc[i][j] = 0.0f;

    // tile loader: 128 rows x 16 k, float4 along K, stored transposed [k][row]
    #define LOAD_TILE(SM, GPTR, ROW0, KOFF, BUF)                                  \
        {                                                                         \
            _Pragma("unroll")                                                     \
            for (int it = 0; it < 2; it++) {                                      \
                int lin = tid + it * 256;                                         \
                int row = lin >> 2;                                               \
                int kq  = (lin & 3) * 4;                                          \
                float4 v = *(const float4*)&GPTR[(size_t)(ROW0 + row) * K_SZ +    \
                                                 (KOFF) + kq];                    \
                SM[BUF][kq + 0][row] = v.x;                                       \
                SM[BUF][kq + 1][row] = v.y;                                       \
                SM[BUF][kq + 2][row] = v.z;                                       \
                SM[BUF][kq + 3][row] = v.w;                                       \
            }                                                                     \
        }

    LOAD_TILE(As, g_A, m0, 0, 0)
    LOAD_TILE(Ws, g_W, n0, 0, 0)
    __syncthreads();

    for (int kt = 0; kt < NKT; kt++) {
        int cbuf = kt & 1;
        if (kt < NKT - 1) {
            int nbuf = cbuf ^ 1;
            int koff = (kt + 1) * BK;
            LOAD_TILE(As, g_A, m0, koff, nbuf)
            LOAD_TILE(Ws, g_W, n0, koff, nbuf)
        }
        #pragma unroll
        for (int kk = 0; kk < BK; kk++) {
            float a[8], bb[8];
            #pragma unroll
            for (int i = 0; i < 8; i++) a[i]  = As[cbuf][kk][ty * 8 + i];
            #pragma unroll
            for (int j = 0; j < 8; j++) bb[j] = Ws[cbuf][kk][tx * 8 + j];
            #pragma unroll
            for (int i = 0; i < 8; i++)
                #pragma unroll
                for (int j = 0; j < 8; j++)
                    acc[i][j] = fmaf(a[i], bb[j], acc[i][j]);
        }
        __syncthreads();
    }

    // epilogue
    // OFF = -0.5*256*log(2*pi) + log(1/4096)
    const float OFF = -235.24826450039622f - 8.317766166719343f;
    float cc[8];
    #pragma unroll
    for (int j = 0; j < 8; j++) cc[j] = g_constc[n0 + tx * 8 + j];

    #pragma unroll
    for (int i = 0; i < 8; i++) {
        int row = m0 + ty * 8 + i;
        float4 o0, o1;
        o0.x = -0.5f * (acc[i][0] + cc[0]) + OFF;
        o0.y = -0.5f * (acc[i][1] + cc[1]) + OFF;
        o0.z = -0.5f * (acc[i][2] + cc[2]) + OFF;
        o0.w = -0.5f * (acc[i][3] + cc[3]) + OFF;
        o1.x = -0.5f * (acc[i][4] + cc[4]) + OFF;
        o1.y = -0.5f * (acc[i][5] + cc[5]) + OFF;
        o1.z = -0.5f * (acc[i][6] + cc[6]) + OFF;
        o1.w = -0.5f * (acc[i][7] + cc[7]) + OFF;
        float* op = out + (size_t)row * C_SZ + n0 + tx * 8;
        *(float4*)(op)     = o0;
        *(float4*)(op + 4) = o1;
    }
}

// ------------------------------ softmax / argmax ------------------------------
__global__ void __launch_bounds__(256)
softmax_rows_kernel(const float* __restrict__ logits,
                    float* __restrict__ probs,
                    float* __restrict__ pred) {
    const int b = blockIdx.x;
    const int tid = threadIdx.x;
    const float* row = logits + (size_t)b * C_SZ;

    __shared__ float sm[256];
    __shared__ int   si[256];
    __shared__ float ss[256];

    // pass 1: max + argmax (first occurrence on ties, like jnp.argmax)
    float m = -INFINITY;
    int mi = 0;
    for (int c = tid; c < C_SZ; c += 256) {
        float v = row[c];
        if (v > m) { m = v; mi = c; }
    }
    sm[tid] = m; si[tid] = mi;
    __syncthreads();
    #pragma unroll
    for (int s = 128; s > 0; s >>= 1) {
        if (tid < s) {
            if (sm[tid + s] > sm[tid] ||
                (sm[tid + s] == sm[tid] && si[tid + s] < si[tid])) {
                sm[tid] = sm[tid + s];
                si[tid] = si[tid + s];
            }
        }
        __syncthreads();
    }
    const float rmax = sm[0];
    const int   amax = si[0];

    // pass 2: sum of exp
    float s = 0.0f;
    for (int c = tid; c < C_SZ; c += 256) s += expf(row[c] - rmax);
    ss[tid] = s;
    __syncthreads();
    #pragma unroll
    for (int st = 128; st > 0; st >>= 1) {
        if (tid < st) ss[tid] += ss[tid + st];
        __syncthreads();
    }
    const float inv = 1.0f / ss[0];

    // pass 3: write probabilities
    for (int c = tid; c < C_SZ; c += 256)
        probs[(size_t)b * C_SZ + c] = expf(row[c] - rmax) * inv;

    if (tid == 0) pred[b] = (float)amax;
}

// ------------------------------ launch ------------------------------
extern "C" void kernel_launch(void* const* d_in, const int* in_sizes, int n_in,
                              void* d_out, int out_size) {
    const float* z      = (const float*)d_in[0];
    const float* mu     = (const float*)d_in[1];
    const float* logvar = (const float*)d_in[2];
    float* out = (float*)d_out;

    float* logits = out;                               // [B, C]
    float* probs  = out + (size_t)B_SZ * C_SZ;         // [B, C]
    float* pred   = out + (size_t)2 * B_SZ * C_SZ;     // [B]

    // prep
    {
        int n = B_SZ * D_SZ;
        prep_A_kernel<<<(n + 255) / 256, 256>>>(z);
        prep_W_kernel<<<C_SZ, 256>>>(mu, logvar);
    }

    // GEMM -> logits
    {
        dim3 grid(C_SZ / BN, B_SZ / BM);   // (32, 128)
        gemm_logits_kernel<<<grid, 256>>>(logits);
    }

    // softmax + argmax
    softmax_rows_kernel<<<B_SZ, 256>>>(logits, probs, pred);
}

// round 3
// speedup vs baseline: 1.2625x; 1.2625x over previous
#include <cuda_runtime.h>
#include <cstdint>
#include <math.h>

// ---------------- problem shape ----------------
#define B_SZ 16384
#define C_SZ 4096
#define D_SZ 256
#define KTOT 1536          // 3 * 2 * D : [Ahi|Ahi|Alo] x [Whi|Wlo|Whi]

// ---------------- GEMM tile ----------------
#define BM 256
#define BN 128
#define BK 32
#define NKT (KTOT / BK)    // 48
#define NTHREADS 512
#define ROWSTRIDE 36       // floats per smem row (pad 4 -> 144B, 16B aligned, conflict-free)
#define A_STG (BM * ROWSTRIDE)            // floats
#define B_STG (BN * ROWSTRIDE)
#define STG_FLOATS (A_STG + B_STG)        // 13824
#define NSTAGES 3
#define SMEM_BYTES (NSTAGES * STG_FLOATS * 4)   // 165888

// -------- scratch (__device__ globals; no allocation allowed) --------
__device__ float g_A2[(size_t)B_SZ * KTOT];   // [B][1536]
__device__ float g_W2[(size_t)C_SZ * KTOT];   // [C][1536]
__device__ float g_constc[C_SZ];

// ---------------- helpers ----------------
__device__ __forceinline__ float tf32_hi(float x) {
    uint32_t h;
    asm("cvt.rna.tf32.f32 %0, %1;" : "=r"(h) : "f"(x));
    return __uint_as_float(h);
}
__device__ __forceinline__ uint32_t smem_u32(const void* p) {
    uint32_t a;
    asm("{ .reg .u64 t; cvta.to.shared.u64 t, %1; cvt.u32.u64 %0, t; }" : "=r"(a) : "l"(p));
    return a;
}
__device__ __forceinline__ void cp16(uint32_t dst, const float* src) {
    asm volatile("cp.async.cg.shared.global [%0], [%1], 16;" :: "r"(dst), "l"(src));
}
#define CP_COMMIT() asm volatile("cp.async.commit_group;" ::: "memory")
#define CP_WAIT2()  asm volatile("cp.async.wait_group 2;" ::: "memory")

__device__ __forceinline__ void mma_tf32(float* d, const float* a, const float* b) {
    uint32_t a0 = __float_as_uint(a[0]), a1 = __float_as_uint(a[1]);
    uint32_t a2 = __float_as_uint(a[2]), a3 = __float_as_uint(a[3]);
    uint32_t b0 = __float_as_uint(b[0]), b1 = __float_as_uint(b[1]);
    asm volatile(
        "mma.sync.aligned.m16n8k8.row.col.f32.tf32.tf32.f32 "
        "{%0,%1,%2,%3}, {%4,%5,%6,%7}, {%8,%9}, {%0,%1,%2,%3};"
        : "+f"(d[0]), "+f"(d[1]), "+f"(d[2]), "+f"(d[3])
        : "r"(a0), "r"(a1), "r"(a2), "r"(a3), "r"(b0), "r"(b1));
}

// ---------------- prep kernels ----------------
// A2 row: [hiA(512) | hiA(512) | loA(512)] where Arow = [z^2 | z]
__global__ void prep_A_kernel(const float* __restrict__ z) {
    int b = blockIdx.x;          // one block per B row
    int d = threadIdx.x;         // 0..255
    float v = z[(size_t)b * D_SZ + d];
    float x1 = v * v;
    float h1 = tf32_hi(x1), l1 = x1 - h1;
    float h2 = tf32_hi(v),  l2 = v - h2;
    float* row = g_A2 + (size_t)b * KTOT;
    row[d]          = h1;
    row[256 + d]    = h2;
    row[512 + d]    = h1;
    row[768 + d]    = h2;
    row[1024 + d]   = l1;
    row[1280 + d]   = l2;
}

// W2 row: [hiW(512) | loW(512) | hiW(512)] where Wrow = [inv_var | -2*mu*inv_var]
__global__ void prep_W_kernel(const float* __restrict__ mu,
                              const float* __restrict__ logvar) {
    int c = blockIdx.x;
    int d = threadIdx.x;
    float lv = logvar[(size_t)c * D_SZ + d];
    float m  = mu[(size_t)c * D_SZ + d];
    float iv = expf(-lv);
    float w2 = -2.0f * m * iv;
    float hiv = tf32_hi(iv), liv = iv - hiv;
    float hw2 = tf32_hi(w2), lw2 = w2 - hw2;
    float* row = g_W2 + (size_t)c * KTOT;
    row[d]          = hiv;
    row[256 + d]    = hw2;
    row[512 + d]    = liv;
    row[768 + d]    = lw2;
    row[1024 + d]   = hiv;
    row[1280 + d]   = hw2;

    __shared__ float red[256];
    red[d] = fmaf(m * m, iv, lv);
    __syncthreads();
    #pragma unroll
    for (int s = 128; s > 0; s >>= 1) {
        if (d < s) red[d] += red[d + s];
        __syncthreads();
    }
    if (d == 0) g_constc[c] = red[0];
}

// ---------------- tf32 mma.sync GEMM ----------------
// logits[b,c] = -0.5*(acc + constc[c]) + OFF
__global__ void __launch_bounds__(NTHREADS, 1)
gemm_tf32_kernel(float* __restrict__ out) {
    extern __shared__ float smem[];
    const int tid = threadIdx.x;
    const int lane = tid & 31;
    const int wid = tid >> 5;        // 0..15
    const int wm = wid >> 1;         // 0..7  -> 32-row band
    const int wn = wid & 1;          // 0..1  -> 64-col band
    const int grp = lane >> 2;       // 0..7
    const int tig = lane & 3;        // 0..3

    const int m0 = blockIdx.y * BM;
    const int n0 = blockIdx.x * BN;

    const uint32_t sb = smem_u32(smem);

    // ---- stage loader (cp.async) ----
    // A: 256 rows x 8 x 16B chunks = 2048 -> 4/thread ; B: 1024 -> 2/thread
    const float* Abase = g_A2 + (size_t)m0 * KTOT;
    const float* Bbase = g_W2 + (size_t)n0 * KTOT;

    #define LOAD_STAGE(slot, kt)                                               \
    {                                                                          \
        uint32_t s0 = sb + (uint32_t)(slot) * (STG_FLOATS * 4);                \
        const float* ag = Abase + (kt) * BK;                                   \
        _Pragma("unroll")                                                      \
        for (int c = 0; c < 4; c++) {                                          \
            int id = tid + c * NTHREADS;                                       \
            int row = id >> 3, col = id & 7;                                   \
            cp16(s0 + (uint32_t)(row * ROWSTRIDE + col * 4) * 4,               \
                 ag + (size_t)row * KTOT + col * 4);                           \
        }                                                                      \
        const float* bg = Bbase + (kt) * BK;                                   \
        uint32_t s1 = s0 + A_STG * 4;                                          \
        _Pragma("unroll")                                                      \
        for (int c = 0; c < 2; c++) {                                          \
            int id = tid + c * NTHREADS;                                       \
            int row = id >> 3, col = id & 7;                                   \
            cp16(s1 + (uint32_t)(row * ROWSTRIDE + col * 4) * 4,               \
                 bg + (size_t)row * KTOT + col * 4);                           \
        }                                                                      \
    }

    LOAD_STAGE(0, 0) CP_COMMIT();
    LOAD_STAGE(1, 1) CP_COMMIT();
    LOAD_STAGE(2, 2) CP_COMMIT();

    float acc[2][8][4];
    #pragma unroll
    for (int i = 0; i < 2; i++)
        #pragma unroll
        for (int j = 0; j < 8; j++)
            #pragma unroll
            for (int q = 0; q < 4; q++) acc[i][j][q] = 0.0f;

    for (int kt = 0; kt < NKT; kt++) {
        CP_WAIT2();
        __syncthreads();

        const int slot = kt % NSTAGES;
        const float* As = smem + slot * STG_FLOATS;
        const float* Bs = As + A_STG;

        #pragma unroll
        for (int kk = 0; kk < 4; kk++) {
            const int kc = kk * 8;
            float a[2][4];
            #pragma unroll
            for (int mt = 0; mt < 2; mt++) {
                int r = wm * 32 + mt * 16 + grp;
                a[mt][0] = As[r * ROWSTRIDE + kc + tig];
                a[mt][1] = As[(r + 8) * ROWSTRIDE + kc + tig];
                a[mt][2] = As[r * ROWSTRIDE + kc + tig + 4];
                a[mt][3] = As[(r + 8) * ROWSTRIDE + kc + tig + 4];
            }
            float b[8][2];
            #pragma unroll
            for (int nt = 0; nt < 8; nt++) {
                int rn = wn * 64 + nt * 8 + grp;
                b[nt][0] = Bs[rn * ROWSTRIDE + kc + tig];
                b[nt][1] = Bs[rn * ROWSTRIDE + kc + tig + 4];
            }
            #pragma unroll
            for (int mt = 0; mt < 2; mt++)
                #pragma unroll
                for (int nt = 0; nt < 8; nt++)
                    mma_tf32(acc[mt][nt], a[mt], b[nt]);
        }

        __syncthreads();
        if (kt + NSTAGES < NKT) { LOAD_STAGE(slot, kt + NSTAGES) }
        CP_COMMIT();   // empty groups near the tail keep wait_group 2 correct
    }

    // ---- epilogue ----
    const float OFF = -235.24826450039622f - 8.317766166719343f;
    #pragma unroll
    for (int mt = 0; mt < 2; mt++) {
        #pragma unroll
        for (int nt = 0; nt < 8; nt++) {
            int row = m0 + wm * 32 + mt * 16 + grp;
            int col = n0 + wn * 64 + nt * 8 + tig * 2;
            float c0 = __ldg(g_constc + col);
            float c1 = __ldg(g_constc + col + 1);
            float2 o0, o1;
            o0.x = fmaf(-0.5f, acc[mt][nt][0] + c0, OFF);
            o0.y = fmaf(-0.5f, acc[mt][nt][1] + c1, OFF);
            o1.x = fmaf(-0.5f, acc[mt][nt][2] + c0, OFF);
            o1.y = fmaf(-0.5f, acc[mt][nt][3] + c1, OFF);
            *(float2*)(out + (size_t)row * C_SZ + col)       = o0;
            *(float2*)(out + (size_t)(row + 8) * C_SZ + col) = o1;
        }
    }
}

// ---------------- softmax / argmax (smem row cache) ----------------
__global__ void __launch_bounds__(256)
softmax_rows_kernel(const float* __restrict__ logits,
                    float* __restrict__ probs,
                    float* __restrict__ pred) {
    const int b = blockIdx.x, tid = threadIdx.x;
    __shared__ float row[C_SZ];
    __shared__ float sm[256]; __shared__ int si[256]; __shared__ float ss[256];

    const float4* src = (const float4*)(logits + (size_t)b * C_SZ);
    #pragma unroll
    for (int i = tid; i < C_SZ / 4; i += 256) ((float4*)row)[i] = src[i];
    __syncthreads();

    float m = -INFINITY; int mi = 0;
    #pragma unroll
    for (int k = 0; k < C_SZ / 256; k++) {
        int c = k * 256 + tid;
        float v = row[c];
        if (v > m) { m = v; mi = c; }
    }
    sm[tid] = m; si[tid] = mi;
    __syncthreads();
    #pragma unroll
    for (int s = 128; s > 0; s >>= 1) {
        if (tid < s) {
            if (sm[tid + s] > sm[tid] ||
                (sm[tid + s] == sm[tid] && si[tid + s] < si[tid])) {
                sm[tid] = sm[tid + s]; si[tid] = si[tid + s];
            }
        }
        __syncthreads();
    }
    const float rmax = sm[0];
    const int amax = si[0];

    float s = 0.0f;
    #pragma unroll
    for (int k = 0; k < C_SZ / 256; k++) s += __expf(row[k * 256 + tid] - rmax);
    ss[tid] = s;
    __syncthreads();
    #pragma unroll
    for (int st = 128; st > 0; st >>= 1) {
        if (tid < st) ss[tid] += ss[tid + st];
        __syncthreads();
    }
    const float inv = 1.0f / ss[0];

    float* dst = probs + (size_t)b * C_SZ;
    #pragma unroll
    for (int k = 0; k < C_SZ / 256; k++) {
        int c = k * 256 + tid;
        dst[c] = __expf(row[c] - rmax) * inv;
    }
    if (tid == 0) pred[b] = (float)amax;
}

// ---------------- launch ----------------
extern "C" void kernel_launch(void* const* d_in, const int* in_sizes, int n_in,
                              void* d_out, int out_size) {
    const float* z      = (const float*)d_in[0];
    const float* mu     = (const float*)d_in[1];
    const float* logvar = (const float*)d_in[2];
    float* out = (float*)d_out;

    float* logits = out;
    float* probs  = out + (size_t)B_SZ * C_SZ;
    float* pred   = out + (size_t)2 * B_SZ * C_SZ;

    cudaFuncSetAttribute(gemm_tf32_kernel,
                         cudaFuncAttributeMaxDynamicSharedMemorySize, SMEM_BYTES);

    prep_A_kernel<<<B_SZ, 256>>>(z);
    prep_W_kernel<<<C_SZ, 256>>>(mu, logvar);

    dim3 grid(C_SZ / BN, B_SZ / BM);   // (32, 64)
    gemm_tf32_kernel<<<grid, NTHREADS, SMEM_BYTES>>>(logits);

    softmax_rows_kernel<<<B_SZ, 256>>>(logits, probs, pred);
}

// round 4
// speedup vs baseline: 1.6630x; 1.3172x over previous
#include <cuda_runtime.h>
#include <cstdint>
#include <math.h>

// ---------------- problem shape ----------------
#define B_SZ 16384
#define C_SZ 4096
#define D_SZ 256
#define K512 512           // packed K: [z^2 | z] x [iv | -2*mu*iv]

// ---------------- GEMM tile ----------------
#define BM 256
#define BN 128
#define BK 32
#define NKT (K512 / BK)    // 16
#define NTHREADS 512

// fragment-packed stage sizes (floats)
#define STAGE_A_FLOATS (16 * 4 * 32 * 8)   // mb16 x kb4 x lane32 x 8 = 16384 (64KB)
#define STAGE_B_FLOATS (16 * 4 * 32 * 4)   // nb16 x kb4 x lane32 x 4 = 8192  (32KB)
#define STAGE_FLOATS (STAGE_A_FLOATS + STAGE_B_FLOATS)       // 24576
#define SMEM_BYTES (2 * STAGE_FLOATS * 4)                    // 196608

// -------- scratch (__device__ globals; no allocation allowed) --------
// A2: [mt=64][kt=16][mb=16][kb=4][lane=32][8]  (hi0,hi1,hi2,hi3, lo0..lo3)
__device__ float g_A2[(size_t)B_SZ * K512 * 2];
// W2: [nt=32][kt=16][nb=16][kb=4][lane=32][4]  (b0hi,b1hi, b0lo,b1lo)
__device__ float g_W2[(size_t)C_SZ * K512 * 2];
__device__ float g_constc[C_SZ];

// ---------------- helpers ----------------
__device__ __forceinline__ float tf32_hi(float x) {
    uint32_t h;
    asm("cvt.rna.tf32.f32 %0, %1;" : "=r"(h) : "f"(x));
    return __uint_as_float(h);
}
__device__ __forceinline__ uint32_t smem_u32(const void* p) {
    uint32_t a;
    asm("{ .reg .u64 t; cvta.to.shared.u64 t, %1; cvt.u32.u64 %0, t; }" : "=r"(a) : "l"(p));
    return a;
}
__device__ __forceinline__ void cp16(uint32_t dst, const float* src) {
    asm volatile("cp.async.cg.shared.global [%0], [%1], 16;" :: "r"(dst), "l"(src));
}
#define CP_COMMIT() asm volatile("cp.async.commit_group;" ::: "memory")
#define CP_WAIT1()  asm volatile("cp.async.wait_group 1;" ::: "memory")
#define CP_WAIT0()  asm volatile("cp.async.wait_group 0;" ::: "memory")

__device__ __forceinline__ void mma_tf32(float* d, const float4& a, float b0, float b1) {
    asm volatile(
        "mma.sync.aligned.m16n8k8.row.col.f32.tf32.tf32.f32 "
        "{%0,%1,%2,%3}, {%4,%5,%6,%7}, {%8,%9}, {%0,%1,%2,%3};"
        : "+f"(d[0]), "+f"(d[1]), "+f"(d[2]), "+f"(d[3])
        : "r"(__float_as_uint(a.x)), "r"(__float_as_uint(a.y)),
          "r"(__float_as_uint(a.z)), "r"(__float_as_uint(a.w)),
          "r"(__float_as_uint(b0)), "r"(__float_as_uint(b1)));
}

// ---------------- prep kernels (write fragment-packed layouts) ----------------
// A logical row k: k<256 -> z^2[d=k]; k>=256 -> z[d=k-256]
__global__ void prep_A_kernel(const float* __restrict__ z) {
    int idx = blockIdx.x * blockDim.x + threadIdx.x;   // 0 .. 64*16*16*4*32-1
    int lane = idx & 31;
    int kb   = (idx >> 5) & 3;
    int mb   = (idx >> 7) & 15;
    int kt   = (idx >> 11) & 15;
    int mt   = idx >> 15;                              // 0..63
    int grp = lane >> 2, tig = lane & 3;

    int r0 = mt * 256 + mb * 16 + grp;
    int k0 = kt * 32 + kb * 8 + tig;                   // 0..511 (k1 = k0+4 same half)
    int half = k0 >> 8;
    int d0 = k0 & 255;

    float v00 = z[(size_t)r0 * D_SZ + d0];
    float v10 = z[(size_t)(r0 + 8) * D_SZ + d0];
    float v01 = z[(size_t)r0 * D_SZ + d0 + 4];
    float v11 = z[(size_t)(r0 + 8) * D_SZ + d0 + 4];
    if (half == 0) { v00 *= v00; v10 *= v10; v01 *= v01; v11 *= v11; }

    float h00 = tf32_hi(v00), h10 = tf32_hi(v10), h01 = tf32_hi(v01), h11 = tf32_hi(v11);
    float4 hi = make_float4(h00, h10, h01, h11);
    float4 lo = make_float4(v00 - h00, v10 - h10, v01 - h01, v11 - h11);

    float4* dst = (float4*)(g_A2 + (size_t)idx * 8);
    dst[0] = hi;
    dst[1] = lo;
}

// W logical row k for class c: k<256 -> iv[d]; k>=256 -> -2*mu*iv[d]
__global__ void prep_W_kernel(const float* __restrict__ mu,
                              const float* __restrict__ logvar) {
    int idx = blockIdx.x * blockDim.x + threadIdx.x;   // 0 .. 32*16*16*4*32-1
    int lane = idx & 31;
    int kb   = (idx >> 5) & 3;
    int nb   = (idx >> 7) & 15;
    int kt   = (idx >> 11) & 15;
    int nt   = idx >> 15;                              // 0..31
    int grp = lane >> 2, tig = lane & 3;

    int c  = nt * 128 + nb * 8 + grp;
    int k0 = kt * 32 + kb * 8 + tig;
    int half = k0 >> 8;
    int d0 = k0 & 255;

    float lv0 = logvar[(size_t)c * D_SZ + d0];
    float lv1 = logvar[(size_t)c * D_SZ + d0 + 4];
    float iv0 = expf(-lv0), iv1 = expf(-lv1);
    float b0, b1;
    if (half == 0) { b0 = iv0; b1 = iv1; }
    else {
        b0 = -2.0f * mu[(size_t)c * D_SZ + d0] * iv0;
        b1 = -2.0f * mu[(size_t)c * D_SZ + d0 + 4] * iv1;
    }
    float h0 = tf32_hi(b0), h1 = tf32_hi(b1);
    float4* dst = (float4*)(g_W2 + (size_t)idx * 4);
    dst[0] = make_float4(h0, h1, b0 - h0, b1 - h1);
}

__global__ void prep_const_kernel(const float* __restrict__ mu,
                                  const float* __restrict__ logvar) {
    int c = blockIdx.x, d = threadIdx.x;
    float lv = logvar[(size_t)c * D_SZ + d];
    float m  = mu[(size_t)c * D_SZ + d];
    float iv = expf(-lv);
    __shared__ float red[256];
    red[d] = fmaf(m * m, iv, lv);
    __syncthreads();
    #pragma unroll
    for (int s = 128; s > 0; s >>= 1) {
        if (d < s) red[d] += red[d + s];
        __syncthreads();
    }
    if (d == 0) g_constc[c] = red[0];
}

// ---------------- tf32 mma.sync GEMM (3-product split, shared fragments) ----------------
__global__ void __launch_bounds__(NTHREADS, 1)
gemm_tf32_kernel(float* __restrict__ out) {
    extern __shared__ float smem[];
    const int tid = threadIdx.x;
    const int lane = tid & 31;
    const int wid = tid >> 5;        // 0..15
    const int wm = wid >> 1;         // 0..7  (32-row band)
    const int wn = wid & 1;          // 0..1  (64-col band)
    const int grp = lane >> 2;
    const int tig = lane & 3;

    const int nt = blockIdx.x;       // 0..31
    const int mt = blockIdx.y;       // 0..63
    const uint32_t sb = smem_u32(smem);

    const float* Abase = g_A2 + (size_t)(mt * NKT) * STAGE_A_FLOATS;
    const float* Bbase = g_W2 + (size_t)(nt * NKT) * STAGE_B_FLOATS;

    // linear stage copy: layouts in gmem and smem are identical
    #define LOAD_STAGE(slot, kt)                                               \
    {                                                                          \
        uint32_t s0 = sb + (uint32_t)(slot) * (STAGE_FLOATS * 4);              \
        const float* ag = Abase + (size_t)(kt) * STAGE_A_FLOATS;               \
        _Pragma("unroll")                                                      \
        for (int c = 0; c < 8; c++) {                                          \
            int id = tid + c * NTHREADS;                                       \
            cp16(s0 + (uint32_t)id * 16, ag + (size_t)id * 4);                 \
        }                                                                      \
        uint32_t s1 = s0 + STAGE_A_FLOATS * 4;                                 \
        const float* bg = Bbase + (size_t)(kt) * STAGE_B_FLOATS;               \
        _Pragma("unroll")                                                      \
        for (int c = 0; c < 4; c++) {                                          \
            int id = tid + c * NTHREADS;                                       \
            cp16(s1 + (uint32_t)id * 16, bg + (size_t)id * 4);                 \
        }                                                                      \
    }

    float acc[2][8][4];
    #pragma unroll
    for (int i = 0; i < 2; i++)
        #pragma unroll
        for (int j = 0; j < 8; j++)
            #pragma unroll
            for (int q = 0; q < 4; q++) acc[i][j][q] = 0.0f;

    LOAD_STAGE(0, 0) CP_COMMIT();

    for (int kt = 0; kt < NKT; kt++) {
        const int slot = kt & 1;
        __syncthreads();                 // all warps done reading slot^1
        if (kt + 1 < NKT) {
            LOAD_STAGE(slot ^ 1, kt + 1) CP_COMMIT();
            CP_WAIT1();
        } else {
            CP_WAIT0();
        }
        __syncthreads();                 // stage (kt) visible to all

        const float* As = smem + slot * STAGE_FLOATS;
        const float* Bs = As + STAGE_A_FLOATS;

        #pragma unroll
        for (int kk = 0; kk < 4; kk++) {
            float4 ahi[2], alo[2];
            #pragma unroll
            for (int ml = 0; ml < 2; ml++) {
                int mb = wm * 2 + ml;
                const float4* ap = (const float4*)(As + ((mb * 4 + kk) * 32 + lane) * 8);
                ahi[ml] = ap[0];
                alo[ml] = ap[1];
            }
            #pragma unroll
            for (int ntl = 0; ntl < 8; ntl++) {
                int nb = wn * 8 + ntl;
                float4 b = *(const float4*)(Bs + ((nb * 4 + kk) * 32 + lane) * 4);
                // hi*hi, hi*lo, lo*hi
                mma_tf32(acc[0][ntl], ahi[0], b.x, b.y);
                mma_tf32(acc[1][ntl], ahi[1], b.x, b.y);
                mma_tf32(acc[0][ntl], ahi[0], b.z, b.w);
                mma_tf32(acc[1][ntl], ahi[1], b.z, b.w);
                mma_tf32(acc[0][ntl], alo[0], b.x, b.y);
                mma_tf32(acc[1][ntl], alo[1], b.x, b.y);
            }
        }
    }

    // ---- epilogue ----
    const float OFF = -235.24826450039622f - 8.317766166719343f;
    const int m0 = mt * BM, n0 = nt * BN;
    #pragma unroll
    for (int ml = 0; ml < 2; ml++) {
        #pragma unroll
        for (int ntl = 0; ntl < 8; ntl++) {
            int row = m0 + wm * 32 + ml * 16 + grp;
            int col = n0 + wn * 64 + ntl * 8 + tig * 2;
            float c0 = __ldg(g_constc + col);
            float c1 = __ldg(g_constc + col + 1);
            float2 o0, o1;
            o0.x = fmaf(-0.5f, acc[ml][ntl][0] + c0, OFF);
            o0.y = fmaf(-0.5f, acc[ml][ntl][1] + c1, OFF);
            o1.x = fmaf(-0.5f, acc[ml][ntl][2] + c0, OFF);
            o1.y = fmaf(-0.5f, acc[ml][ntl][3] + c1, OFF);
            *(float2*)(out + (size_t)row * C_SZ + col)       = o0;
            *(float2*)(out + (size_t)(row + 8) * C_SZ + col) = o1;
        }
    }
}

// ---------------- softmax / argmax (smem row cache) ----------------
__global__ void __launch_bounds__(256)
softmax_rows_kernel(const float* __restrict__ logits,
                    float* __restrict__ probs,
                    float* __restrict__ pred) {
    const int b = blockIdx.x, tid = threadIdx.x;
    __shared__ float row[C_SZ];
    __shared__ float sm[256]; __shared__ int si[256]; __shared__ float ss[256];

    const float4* src = (const float4*)(logits + (size_t)b * C_SZ);
    #pragma unroll
    for (int i = tid; i < C_SZ / 4; i += 256) ((float4*)row)[i] = src[i];
    __syncthreads();

    float m = -INFINITY; int mi = 0;
    #pragma unroll
    for (int k = 0; k < C_SZ / 256; k++) {
        int c = k * 256 + tid;
        float v = row[c];
        if (v > m) { m = v; mi = c; }
    }
    sm[tid] = m; si[tid] = mi;
    __syncthreads();
    #pragma unroll
    for (int s = 128; s > 0; s >>= 1) {
        if (tid < s) {
            if (sm[tid + s] > sm[tid] ||
                (sm[tid + s] == sm[tid] && si[tid + s] < si[tid])) {
                sm[tid] = sm[tid + s]; si[tid] = si[tid + s];
            }
        }
        __syncthreads();
    }
    const float rmax = sm[0];
    const int amax = si[0];

    float s = 0.0f;
    #pragma unroll
    for (int k = 0; k < C_SZ / 256; k++) s += __expf(row[k * 256 + tid] - rmax);
    ss[tid] = s;
    __syncthreads();
    #pragma unroll
    for (int st = 128; st > 0; st >>= 1) {
        if (tid < st) ss[tid] += ss[tid + st];
        __syncthreads();
    }
    const float inv = 1.0f / ss[0];

    float* dst = probs + (size_t)b * C_SZ;
    #pragma unroll
    for (int k = 0; k < C_SZ / 256; k++) {
        int c = k * 256 + tid;
        dst[c] = __expf(row[c] - rmax) * inv;
    }
    if (tid == 0) pred[b] = (float)amax;
}

// ---------------- launch ----------------
extern "C" void kernel_launch(void* const* d_in, const int* in_sizes, int n_in,
                              void* d_out, int out_size) {
    const float* z      = (const float*)d_in[0];
    const float* mu     = (const float*)d_in[1];
    const float* logvar = (const float*)d_in[2];
    float* out = (float*)d_out;

    float* logits = out;
    float* probs  = out + (size_t)B_SZ * C_SZ;
    float* pred   = out + (size_t)2 * B_SZ * C_SZ;

    cudaFuncSetAttribute(gemm_tf32_kernel,
                         cudaFuncAttributeMaxDynamicSharedMemorySize, SMEM_BYTES);

    {
        int nA = 64 * 16 * 16 * 4 * 32;    // 2,097,152 threads
        prep_A_kernel<<<nA / 256, 256>>>(z);
        int nW = 32 * 16 * 16 * 4 * 32;    // 1,048,576
        prep_W_kernel<<<nW / 256, 256>>>(mu, logvar);
        prep_const_kernel<<<C_SZ, 256>>>(mu, logvar);
    }

    dim3 grid(C_SZ / BN, B_SZ / BM);       // (32, 64)
    gemm_tf32_kernel<<<grid, NTHREADS, SMEM_BYTES>>>(logits);

    softmax_rows_kernel<<<B_SZ, 256>>>(logits, probs, pred);
}

// round 6
// speedup vs baseline: 2.2235x; 1.3371x over previous
#include <cuda_runtime.h>
#include <cuda_bf16.h>
#include <cstdint>
#include <math.h>

// ---------------- problem shape ----------------
#define B_SZ 16384
#define C_SZ 4096
#define D_SZ 256
#define K512 512           // logical K: [z^2 | z] x [iv | -2*mu*iv]

// ---------------- GEMM tile ----------------
#define BM 256
#define BN 128
#define NKT 16             // K512 / 32
#define NTHREADS 512

// stage layout (float4 units):
//  A_tf32 : [mb16][kk4][lane32] float4            -> 2048 float4
//  A_bf16 : [mb16][kb4][lane32] uint4 (8 bf16)    -> 2048
//  W_tf32 : [nbp8][kk4][lane32] float4            -> 1024
//  W_bf16 : [nbp8][kb4][lane32] uint4             -> 1024
#define STAGE_F4 6144
#define STAGE_BYTES (STAGE_F4 * 16)                 // 98304
#define SMEM_BYTES (2 * STAGE_BYTES)                // 196608

// -------- scratch (__device__ globals; no allocation allowed) --------
__device__ float4 g_A2[(size_t)64 * NKT * 4096];    // 64 MB: [mt][kt][tf 2048 | bf 2048]
__device__ float4 g_W2[(size_t)32 * NKT * 2048];    // 16 MB: [nt][kt][tf 1024 | bf 1024]
__device__ float g_constc[C_SZ];

// ---------------- helpers ----------------
__device__ __forceinline__ float tf32_hi(float x) {
    uint32_t h;
    asm("cvt.rna.tf32.f32 %0, %1;" : "=r"(h) : "f"(x));
    return __uint_as_float(h);
}
__device__ __forceinline__ uint32_t pack_bf16(float e, float o) {
    __nv_bfloat162 t = __floats2bfloat162_rn(e, o);   // .x = low 16 bits
    return *(uint32_t*)&t;
}
__device__ __forceinline__ uint32_t smem_u32(const void* p) {
    uint32_t a;
    asm("{ .reg .u64 t; cvta.to.shared.u64 t, %1; cvt.u32.u64 %0, t; }" : "=r"(a) : "l"(p));
    return a;
}
__device__ __forceinline__ void cp16(uint32_t dst, const void* src) {
    asm volatile("cp.async.cg.shared.global [%0], [%1], 16;" :: "r"(dst), "l"(src));
}
#define CP_COMMIT() asm volatile("cp.async.commit_group;" ::: "memory")
#define CP_WAIT0()  asm volatile("cp.async.wait_group 0;" ::: "memory")

__device__ __forceinline__ void mma_tf32(float* d, const float4& a, float b0, float b1) {
    asm volatile(
        "mma.sync.aligned.m16n8k8.row.col.f32.tf32.tf32.f32 "
        "{%0,%1,%2,%3}, {%4,%5,%6,%7}, {%8,%9}, {%0,%1,%2,%3};"
        : "+f"(d[0]), "+f"(d[1]), "+f"(d[2]), "+f"(d[3])
        : "r"(__float_as_uint(a.x)), "r"(__float_as_uint(a.y)),
          "r"(__float_as_uint(a.z)), "r"(__float_as_uint(a.w)),
          "r"(__float_as_uint(b0)), "r"(__float_as_uint(b1)));
}
__device__ __forceinline__ void mma_bf16(float* d, const uint4& a, uint32_t b0, uint32_t b1) {
    asm volatile(
        "mma.sync.aligned.m16n8k16.row.col.f32.bf16.bf16.f32 "
        "{%0,%1,%2,%3}, {%4,%5,%6,%7}, {%8,%9}, {%0,%1,%2,%3};"
        : "+f"(d[0]), "+f"(d[1]), "+f"(d[2]), "+f"(d[3])
        : "r"(a.x), "r"(a.y), "r"(a.z), "r"(a.w), "r"(b0), "r"(b1));
}

// logical operand values
__device__ __forceinline__ float Aval(const float* __restrict__ z, int r, int k) {
    float v = __ldg(z + (size_t)r * D_SZ + (k & 255));
    return (k < 256) ? v * v : v;
}
__device__ __forceinline__ float Wval(const float* __restrict__ mu,
                                      const float* __restrict__ lv, int c, int k) {
    int d = k & 255;
    float l = __ldg(lv + (size_t)c * D_SZ + d);
    float iv = expf(-l);
    return (k < 256) ? iv : -2.0f * __ldg(mu + (size_t)c * D_SZ + d) * iv;
}

// ---------------- prep kernels ----------------
// tf32 A fragments: hi(a)
__global__ void prep_Atf_kernel(const float* __restrict__ z) {
    int idx = blockIdx.x * blockDim.x + threadIdx.x;   // 64*16*16*4*32 = 2,097,152
    int lane = idx & 31, kk = (idx >> 5) & 3, mb = (idx >> 7) & 15;
    int kt = (idx >> 11) & 15, mt = idx >> 15;
    int grp = lane >> 2, tig = lane & 3;
    int r0 = mt * 256 + mb * 16 + grp;
    int k0 = kt * 32 + kk * 8 + tig;
    float4 o;
    o.x = tf32_hi(Aval(z, r0, k0));
    o.y = tf32_hi(Aval(z, r0 + 8, k0));
    o.z = tf32_hi(Aval(z, r0, k0 + 4));
    o.w = tf32_hi(Aval(z, r0 + 8, k0 + 4));
    g_A2[(size_t)(mt * NKT + kt) * 4096 + (mb * 4 + kk) * 32 + lane] = o;
}

// bf16 A fragments: kb<2 -> bf16(lo_a); kb>=2 -> bf16(hi_a)
__global__ void prep_Abf_kernel(const float* __restrict__ z) {
    int idx = blockIdx.x * blockDim.x + threadIdx.x;   // 2,097,152
    int lane = idx & 31, kb = (idx >> 5) & 3, mb = (idx >> 7) & 15;
    int kt = (idx >> 11) & 15, mt = idx >> 15;
    int grp = lane >> 2, tig = lane & 3;
    int r0 = mt * 256 + mb * 16 + grp;
    int hsel = kb >> 1;
    int kbase = kt * 32 + (kb & 1) * 16;
    int ke0 = kbase + tig * 2;
    int ke1 = kbase + 8 + tig * 2;

    #define AE(r, k) ({ float _a = Aval(z, (r), (k)); float _h = tf32_hi(_a); \
                        hsel ? _h : (_a - _h); })
    uint4 o;
    o.x = pack_bf16(AE(r0, ke0),     AE(r0, ke0 + 1));
    o.y = pack_bf16(AE(r0 + 8, ke0), AE(r0 + 8, ke0 + 1));
    o.z = pack_bf16(AE(r0, ke1),     AE(r0, ke1 + 1));
    o.w = pack_bf16(AE(r0 + 8, ke1), AE(r0 + 8, ke1 + 1));
    #undef AE
    ((uint4*)g_A2)[(size_t)(mt * NKT + kt) * 4096 + 2048 + (mb * 4 + kb) * 32 + lane] = o;
}

// tf32 W fragments (nb pairs): hi(w)
// field layout: lane[0:5) kk[5:7) nbp[7:10) kt[10:14) nt[14:)   (FIXED shifts)
__global__ void prep_Wtf_kernel(const float* __restrict__ mu,
                                const float* __restrict__ logvar) {
    int idx = blockIdx.x * blockDim.x + threadIdx.x;   // 32*16*8*4*32 = 524,288
    int lane = idx & 31, kk = (idx >> 5) & 3, nbp = (idx >> 7) & 7;
    int kt = (idx >> 10) & 15, nt = idx >> 14;
    int grp = lane >> 2, tig = lane & 3;
    int c0 = nt * 128 + nbp * 16 + grp;
    int c1 = c0 + 8;
    int k0 = kt * 32 + kk * 8 + tig;
    float4 o;
    o.x = tf32_hi(Wval(mu, logvar, c0, k0));
    o.y = tf32_hi(Wval(mu, logvar, c0, k0 + 4));
    o.z = tf32_hi(Wval(mu, logvar, c1, k0));
    o.w = tf32_hi(Wval(mu, logvar, c1, k0 + 4));
    g_W2[(size_t)(nt * NKT + kt) * 2048 + (nbp * 4 + kk) * 32 + lane] = o;
}

// bf16 W fragments: kb<2 -> bf16(hi_w) (pairs lo_a); kb>=2 -> bf16(lo_w) (pairs hi_a)
__global__ void prep_Wbf_kernel(const float* __restrict__ mu,
                                const float* __restrict__ logvar) {
    int idx = blockIdx.x * blockDim.x + threadIdx.x;   // 524,288
    int lane = idx & 31, kb = (idx >> 5) & 3, nbp = (idx >> 7) & 7;
    int kt = (idx >> 10) & 15, nt = idx >> 14;         // FIXED shifts
    int grp = lane >> 2, tig = lane & 3;
    int c0 = nt * 128 + nbp * 16 + grp;
    int c1 = c0 + 8;
    int hsel = kb >> 1;
    int kbase = kt * 32 + (kb & 1) * 16;
    int ke0 = kbase + tig * 2;
    int ke1 = kbase + 8 + tig * 2;

    #define WE(c, k) ({ float _w = Wval(mu, logvar, (c), (k)); float _h = tf32_hi(_w); \
                        hsel ? (_w - _h) : _h; })
    uint4 o;
    o.x = pack_bf16(WE(c0, ke0), WE(c0, ke0 + 1));
    o.y = pack_bf16(WE(c0, ke1), WE(c0, ke1 + 1));
    o.z = pack_bf16(WE(c1, ke0), WE(c1, ke0 + 1));
    o.w = pack_bf16(WE(c1, ke1), WE(c1, ke1 + 1));
    #undef WE
    ((uint4*)g_W2)[(size_t)(nt * NKT + kt) * 2048 + 1024 + (nbp * 4 + kb) * 32 + lane] = o;
}

__global__ void prep_const_kernel(const float* __restrict__ mu,
                                  const float* __restrict__ logvar) {
    int c = blockIdx.x, d = threadIdx.x;
    float lv = logvar[(size_t)c * D_SZ + d];
    float m  = mu[(size_t)c * D_SZ + d];
    float iv = expf(-lv);
    __shared__ float red[256];
    red[d] = fmaf(m * m, iv, lv);
    __syncthreads();
    #pragma unroll
    for (int s = 128; s > 0; s >>= 1) {
        if (d < s) red[d] += red[d + s];
        __syncthreads();
    }
    if (d == 0) g_constc[c] = red[0];
}

// ---------------- GEMM: tf32 hi*hi + bf16 cross terms ----------------
__global__ void __launch_bounds__(NTHREADS, 1)
gemm_hybrid_kernel(float* __restrict__ out) {
    extern __shared__ float4 smem4[];
    const int tid = threadIdx.x;
    const int lane = tid & 31;
    const int wid = tid >> 5;        // 0..15
    const int wm = wid >> 1;         // 0..7  (32-row band)
    const int wn = wid & 1;          // 0..1  (64-col band)
    const int grp = lane >> 2;
    const int tig = lane & 3;

    const int nt = blockIdx.x;       // 0..31
    const int mt = blockIdx.y;       // 0..63
    const uint32_t sb = smem_u32(smem4);

    const float4* Abase = g_A2 + (size_t)mt * NKT * 4096;
    const float4* Wbase = g_W2 + (size_t)nt * NKT * 2048;

    #define LOAD_STAGE(slot, kt)                                               \
    {                                                                          \
        uint32_t s0 = sb + (uint32_t)(slot) * STAGE_BYTES;                     \
        const float4* ag = Abase + (size_t)(kt) * 4096;                        \
        _Pragma("unroll")                                                      \
        for (int c = 0; c < 8; c++) {                                          \
            int id = tid + c * NTHREADS;                                       \
            cp16(s0 + (uint32_t)id * 16, ag + id);                             \
        }                                                                      \
        const float4* wg = Wbase + (size_t)(kt) * 2048;                        \
        uint32_t s1 = s0 + 4096 * 16;                                          \
        _Pragma("unroll")                                                      \
        for (int c = 0; c < 4; c++) {                                          \
            int id = tid + c * NTHREADS;                                       \
            cp16(s1 + (uint32_t)id * 16, wg + id);                             \
        }                                                                      \
    }

    float acc[2][8][4];
    #pragma unroll
    for (int i = 0; i < 2; i++)
        #pragma unroll
        for (int j = 0; j < 8; j++)
            #pragma unroll
            for (int q = 0; q < 4; q++) acc[i][j][q] = 0.0f;

    LOAD_STAGE(0, 0) CP_COMMIT();

    for (int kt = 0; kt < NKT; kt++) {
        const int slot = kt & 1;
        CP_WAIT0();                       // this thread's copies for stage kt done
        __syncthreads();                  // all threads' copies visible; prev reads done
        if (kt + 1 < NKT) {
            LOAD_STAGE(slot ^ 1, kt + 1)
            CP_COMMIT();
        }

        const float4* As = smem4 + slot * STAGE_F4;
        const uint4*  Ab = (const uint4*)(As + 2048);
        const float4* Wt = As + 4096;
        const uint4*  Wb = (const uint4*)(As + 5120);

        #pragma unroll
        for (int j = 0; j < 4; j++) {
            float4 ahi0 = As[((wm * 2) * 4 + j) * 32 + lane];
            float4 ahi1 = As[((wm * 2 + 1) * 4 + j) * 32 + lane];
            uint4  ab0  = Ab[((wm * 2) * 4 + j) * 32 + lane];
            uint4  ab1  = Ab[((wm * 2 + 1) * 4 + j) * 32 + lane];
            #pragma unroll
            for (int p = 0; p < 4; p++) {
                float4 wt = Wt[((wn * 4 + p) * 4 + j) * 32 + lane];
                uint4  wb = Wb[((wn * 4 + p) * 4 + j) * 32 + lane];
                mma_tf32(acc[0][2 * p],     ahi0, wt.x, wt.y);
                mma_tf32(acc[0][2 * p + 1], ahi0, wt.z, wt.w);
                mma_tf32(acc[1][2 * p],     ahi1, wt.x, wt.y);
                mma_tf32(acc[1][2 * p + 1], ahi1, wt.z, wt.w);
                mma_bf16(acc[0][2 * p],     ab0, wb.x, wb.y);
                mma_bf16(acc[0][2 * p + 1], ab0, wb.z, wb.w);
                mma_bf16(acc[1][2 * p],     ab1, wb.x, wb.y);
                mma_bf16(acc[1][2 * p + 1], ab1, wb.z, wb.w);
            }
        }
    }

    // ---- epilogue ----
    const float OFF = -235.24826450039622f - 8.317766166719343f;
    const int m0 = mt * BM, n0 = nt * BN;
    #pragma unroll
    for (int ml = 0; ml < 2; ml++) {
        #pragma unroll
        for (int ntl = 0; ntl < 8; ntl++) {
            int row = m0 + wm * 32 + ml * 16 + grp;
            int col = n0 + wn * 64 + ntl * 8 + tig * 2;
            float c0 = __ldg(g_constc + col);
            float c1 = __ldg(g_constc + col + 1);
            float2 o0, o1;
            o0.x = fmaf(-0.5f, acc[ml][ntl][0] + c0, OFF);
            o0.y = fmaf(-0.5f, acc[ml][ntl][1] + c1, OFF);
            o1.x = fmaf(-0.5f, acc[ml][ntl][2] + c0, OFF);
            o1.y = fmaf(-0.5f, acc[ml][ntl][3] + c1, OFF);
            *(float2*)(out + (size_t)row * C_SZ + col)       = o0;
            *(float2*)(out + (size_t)(row + 8) * C_SZ + col) = o1;
        }
    }
}

// ---------------- softmax / argmax (smem row cache) ----------------
__global__ void __launch_bounds__(256)
softmax_rows_kernel(const float* __restrict__ logits,
                    float* __restrict__ probs,
                    float* __restrict__ pred) {
    const int b = blockIdx.x, tid = threadIdx.x;
    __shared__ float row[C_SZ];
    __shared__ float sm[256]; __shared__ int si[256]; __shared__ float ss[256];

    const float4* src = (const float4*)(logits + (size_t)b * C_SZ);
    #pragma unroll
    for (int i = tid; i < C_SZ / 4; i += 256) ((float4*)row)[i] = src[i];
    __syncthreads();

    float m = -INFINITY; int mi = 0;
    #pragma unroll
    for (int k = 0; k < C_SZ / 256; k++) {
        int c = k * 256 + tid;
        float v = row[c];
        if (v > m) { m = v; mi = c; }
    }
    sm[tid] = m; si[tid] = mi;
    __syncthreads();
    #pragma unroll
    for (int s = 128; s > 0; s >>= 1) {
        if (tid < s) {
            if (sm[tid + s] > sm[tid] ||
                (sm[tid + s] == sm[tid] && si[tid + s] < si[tid])) {
                sm[tid] = sm[tid + s]; si[tid] = si[tid + s];
            }
        }
        __syncthreads();
    }
    const float rmax = sm[0];
    const int amax = si[0];

    float s = 0.0f;
    #pragma unroll
    for (int k = 0; k < C_SZ / 256; k++) s += __expf(row[k * 256 + tid] - rmax);
    ss[tid] = s;
    __syncthreads();
    #pragma unroll
    for (int st = 128; st > 0; st >>= 1) {
        if (tid < st) ss[tid] += ss[tid + st];
        __syncthreads();
    }
    const float inv = 1.0f / ss[0];

    float* dst = probs + (size_t)b * C_SZ;
    #pragma unroll
    for (int k = 0; k < C_SZ / 256; k++) {
        int c = k * 256 + tid;
        dst[c] = __expf(row[c] - rmax) * inv;
    }
    if (tid == 0) pred[b] = (float)amax;
}

// ---------------- launch ----------------
extern "C" void kernel_launch(void* const* d_in, const int* in_sizes, int n_in,
                              void* d_out, int out_size) {
    const float* z      = (const float*)d_in[0];
    const float* mu     = (const float*)d_in[1];
    const float* logvar = (const float*)d_in[2];
    float* out = (float*)d_out;

    float* logits = out;
    float* probs  = out + (size_t)B_SZ * C_SZ;
    float* pred   = out + (size_t)2 * B_SZ * C_SZ;

    cudaFuncSetAttribute(gemm_hybrid_kernel,
                         cudaFuncAttributeMaxDynamicSharedMemorySize, SMEM_BYTES);

    {
        int nA = 64 * NKT * 16 * 4 * 32;   // 2,097,152
        prep_Atf_kernel<<<nA / 256, 256>>>(z);
        prep_Abf_kernel<<<nA / 256, 256>>>(z);
        int nW = 32 * NKT * 8 * 4 * 32;    // 524,288
        prep_Wtf_kernel<<<nW / 256, 256>>>(mu, logvar);
        prep_Wbf_kernel<<<nW / 256, 256>>>(mu, logvar);
        prep_const_kernel<<<C_SZ, 256>>>(mu, logvar);
    }

    dim3 grid(C_SZ / BN, B_SZ / BM);       // (32, 64)
    gemm_hybrid_kernel<<<grid, NTHREADS, SMEM_BYTES>>>(logits);

    softmax_rows_kernel<<<B_SZ, 256>>>(logits, probs, pred);
}

// round 7
// speedup vs baseline: 2.7006x; 1.2146x over previous
#include <cuda_runtime.h>
#include <cuda_bf16.h>
#include <cuda_fp16.h>
#include <cstdint>
#include <math.h>

// ---------------- problem shape ----------------
#define B_SZ 16384
#define C_SZ 4096
#define D_SZ 256
// logical K = 512 : A = [z^2 | z],  W = [iv | -2*mu*iv]

// ---------------- GEMM tile ----------------
#define BM 256
#define BN 128
#define NKT 16             // k-tiles of 32
#define NTHREADS 512

// tile images (uint4 units):
//  A tile: [fp16 hi: mb16 x kb2 x lane32 = 1024 | bf16: mb16 x kb4 x lane32 = 2048] = 3072
//  W tile: [fp16 hi: nbp8 x kb2 x lane32 = 512  | bf16: nbp8 x kb4 x lane32 = 1024] = 1536
#define A_TILE_U4 3072
#define W_TILE_U4 1536
#define STAGE_U4 (A_TILE_U4 + W_TILE_U4)            // 4608 -> 72KB
#define STAGE_BYTES (STAGE_U4 * 16)
#define NSTAGES 3
#define SMEM_BYTES (NSTAGES * STAGE_BYTES)          // 221184

// -------- scratch (__device__ globals; no allocation allowed) --------
__device__ uint4 g_A[(size_t)64 * NKT * A_TILE_U4];   // 48 MB
__device__ uint4 g_W[(size_t)32 * NKT * W_TILE_U4];   // 12 MB
__device__ float g_constc[C_SZ];

// ---------------- helpers ----------------
#define FP16_MIN_NORMAL 6.104e-5f

__device__ __forceinline__ float fp16_hi(float x) {
    // hi part of x representable as a NORMAL fp16 (or exactly 0)
    if (fabsf(x) < FP16_MIN_NORMAL) return 0.0f;
    return __half2float(__float2half_rn(x));
}
__device__ __forceinline__ uint32_t pack_h2(float e, float o) {
    __half2 t;
    t.x = (fabsf(e) < FP16_MIN_NORMAL) ? __half(0.0f) : __float2half_rn(e);
    t.y = (fabsf(o) < FP16_MIN_NORMAL) ? __half(0.0f) : __float2half_rn(o);
    return *(uint32_t*)&t;
}
__device__ __forceinline__ uint32_t pack_bf16(float e, float o) {
    __nv_bfloat162 t = __floats2bfloat162_rn(e, o);   // .x = low 16 bits
    return *(uint32_t*)&t;
}
__device__ __forceinline__ uint32_t smem_u32(const void* p) {
    uint32_t a;
    asm("{ .reg .u64 t; cvta.to.shared.u64 t, %1; cvt.u32.u64 %0, t; }" : "=r"(a) : "l"(p));
    return a;
}
__device__ __forceinline__ void cp16(uint32_t dst, const void* src) {
    asm volatile("cp.async.cg.shared.global [%0], [%1], 16;" :: "r"(dst), "l"(src));
}
#define CP_COMMIT() asm volatile("cp.async.commit_group;" ::: "memory")
#define CP_WAIT1()  asm volatile("cp.async.wait_group 1;" ::: "memory")

__device__ __forceinline__ void mma_f16(float* d, const uint4& a, uint32_t b0, uint32_t b1) {
    asm volatile(
        "mma.sync.aligned.m16n8k16.row.col.f32.f16.f16.f32 "
        "{%0,%1,%2,%3}, {%4,%5,%6,%7}, {%8,%9}, {%0,%1,%2,%3};"
        : "+f"(d[0]), "+f"(d[1]), "+f"(d[2]), "+f"(d[3])
        : "r"(a.x), "r"(a.y), "r"(a.z), "r"(a.w), "r"(b0), "r"(b1));
}
__device__ __forceinline__ void mma_bf16(float* d, const uint4& a, uint32_t b0, uint32_t b1) {
    asm volatile(
        "mma.sync.aligned.m16n8k16.row.col.f32.bf16.bf16.f32 "
        "{%0,%1,%2,%3}, {%4,%5,%6,%7}, {%8,%9}, {%0,%1,%2,%3};"
        : "+f"(d[0]), "+f"(d[1]), "+f"(d[2]), "+f"(d[3])
        : "r"(a.x), "r"(a.y), "r"(a.z), "r"(a.w), "r"(b0), "r"(b1));
}

// logical operand values
__device__ __forceinline__ float Aval(const float* __restrict__ z, int r, int k) {
    float v = __ldg(z + (size_t)r * D_SZ + (k & 255));
    return (k < 256) ? v * v : v;
}
__device__ __forceinline__ float Wval(const float* __restrict__ mu,
                                      const float* __restrict__ lv, int c, int k) {
    int d = k & 255;
    float l = __ldg(lv + (size_t)c * D_SZ + d);
    float iv = expf(-l);
    return (k < 256) ? iv : -2.0f * __ldg(mu + (size_t)c * D_SZ + d) * iv;
}

// ---------------- prep kernels ----------------
// fp16 hi(A): fields lane[0:5) kb[5:6) mb[6:10) kt[10:14) mt[14:)
__global__ void prep_Afp_kernel(const float* __restrict__ z) {
    int idx = blockIdx.x * blockDim.x + threadIdx.x;   // 1,048,576
    int lane = idx & 31, kb = (idx >> 5) & 1, mb = (idx >> 6) & 15;
    int kt = (idx >> 10) & 15, mt = idx >> 14;
    int grp = lane >> 2, tig = lane & 3;
    int r0 = mt * 256 + mb * 16 + grp;
    int kbase = kt * 32 + kb * 16;
    int ke0 = kbase + tig * 2, ke1 = kbase + 8 + tig * 2;
    uint4 o;
    o.x = pack_h2(Aval(z, r0, ke0),     Aval(z, r0, ke0 + 1));
    o.y = pack_h2(Aval(z, r0 + 8, ke0), Aval(z, r0 + 8, ke0 + 1));
    o.z = pack_h2(Aval(z, r0, ke1),     Aval(z, r0, ke1 + 1));
    o.w = pack_h2(Aval(z, r0 + 8, ke1), Aval(z, r0 + 8, ke1 + 1));
    g_A[(size_t)(mt * NKT + kt) * A_TILE_U4 + (mb * 2 + kb) * 32 + lane] = o;
}

// bf16 A: kb<2 -> bf16(lo_a); kb>=2 -> bf16(a)
// fields lane[0:5) kb[5:7) mb[7:11) kt[11:15) mt[15:)
__global__ void prep_Abf_kernel(const float* __restrict__ z) {
    int idx = blockIdx.x * blockDim.x + threadIdx.x;   // 2,097,152
    int lane = idx & 31, kb = (idx >> 5) & 3, mb = (idx >> 7) & 15;
    int kt = (idx >> 11) & 15, mt = idx >> 15;
    int grp = lane >> 2, tig = lane & 3;
    int r0 = mt * 256 + mb * 16 + grp;
    int hsel = kb >> 1;
    int kbase = kt * 32 + (kb & 1) * 16;
    int ke0 = kbase + tig * 2, ke1 = kbase + 8 + tig * 2;

    #define AE(r, k) ({ float _a = Aval(z, (r), (k)); \
                        hsel ? _a : (_a - fp16_hi(_a)); })
    uint4 o;
    o.x = pack_bf16(AE(r0, ke0),     AE(r0, ke0 + 1));
    o.y = pack_bf16(AE(r0 + 8, ke0), AE(r0 + 8, ke0 + 1));
    o.z = pack_bf16(AE(r0, ke1),     AE(r0, ke1 + 1));
    o.w = pack_bf16(AE(r0 + 8, ke1), AE(r0 + 8, ke1 + 1));
    #undef AE
    g_A[(size_t)(mt * NKT + kt) * A_TILE_U4 + 1024 + (mb * 4 + kb) * 32 + lane] = o;
}

// fp16 hi(W): fields lane[0:5) kb[5:6) nbp[6:9) kt[9:13) nt[13:)
__global__ void prep_Wfp_kernel(const float* __restrict__ mu,
                                const float* __restrict__ logvar) {
    int idx = blockIdx.x * blockDim.x + threadIdx.x;   // 262,144
    int lane = idx & 31, kb = (idx >> 5) & 1, nbp = (idx >> 6) & 7;
    int kt = (idx >> 9) & 15, nt = idx >> 13;
    int grp = lane >> 2, tig = lane & 3;
    int c0 = nt * 128 + nbp * 16 + grp;
    int c1 = c0 + 8;
    int kbase = kt * 32 + kb * 16;
    int ke0 = kbase + tig * 2, ke1 = kbase + 8 + tig * 2;
    uint4 o;
    o.x = pack_h2(Wval(mu, logvar, c0, ke0), Wval(mu, logvar, c0, ke0 + 1));
    o.y = pack_h2(Wval(mu, logvar, c0, ke1), Wval(mu, logvar, c0, ke1 + 1));
    o.z = pack_h2(Wval(mu, logvar, c1, ke0), Wval(mu, logvar, c1, ke0 + 1));
    o.w = pack_h2(Wval(mu, logvar, c1, ke1), Wval(mu, logvar, c1, ke1 + 1));
    g_W[(size_t)(nt * NKT + kt) * W_TILE_U4 + (nbp * 2 + kb) * 32 + lane] = o;
}

// bf16 W: kb<2 -> bf16(w); kb>=2 -> bf16(lo_w)
// fields lane[0:5) kb[5:7) nbp[7:10) kt[10:14) nt[14:)
__global__ void prep_Wbf_kernel(const float* __restrict__ mu,
                                const float* __restrict__ logvar) {
    int idx = blockIdx.x * blockDim.x + threadIdx.x;   // 524,288
    int lane = idx & 31, kb = (idx >> 5) & 3, nbp = (idx >> 7) & 7;
    int kt = (idx >> 10) & 15, nt = idx >> 14;
    int grp = lane >> 2, tig = lane & 3;
    int c0 = nt * 128 + nbp * 16 + grp;
    int c1 = c0 + 8;
    int hsel = kb >> 1;
    int kbase = kt * 32 + (kb & 1) * 16;
    int ke0 = kbase + tig * 2, ke1 = kbase + 8 + tig * 2;

    #define WE(c, k) ({ float _w = Wval(mu, logvar, (c), (k)); \
                        hsel ? (_w - fp16_hi(_w)) : _w; })
    uint4 o;
    o.x = pack_bf16(WE(c0, ke0), WE(c0, ke0 + 1));
    o.y = pack_bf16(WE(c0, ke1), WE(c0, ke1 + 1));
    o.z = pack_bf16(WE(c1, ke0), WE(c1, ke0 + 1));
    o.w = pack_bf16(WE(c1, ke1), WE(c1, ke1 + 1));
    #undef WE
    g_W[(size_t)(nt * NKT + kt) * W_TILE_U4 + 512 + (nbp * 4 + kb) * 32 + lane] = o;
}

__global__ void prep_const_kernel(const float* __restrict__ mu,
                                  const float* __restrict__ logvar) {
    int c = blockIdx.x, d = threadIdx.x;
    float lv = logvar[(size_t)c * D_SZ + d];
    float m  = mu[(size_t)c * D_SZ + d];
    float iv = expf(-lv);
    __shared__ float red[256];
    red[d] = fmaf(m * m, iv, lv);
    __syncthreads();
    #pragma unroll
    for (int s = 128; s > 0; s >>= 1) {
        if (d < s) red[d] += red[d + s];
        __syncthreads();
    }
    if (d == 0) g_constc[c] = red[0];
}

// ---------------- GEMM: fp16 hi*hi + bf16 cross terms ----------------
__global__ void __launch_bounds__(NTHREADS, 1)
gemm_hybrid_kernel(float* __restrict__ out) {
    extern __shared__ uint4 smem4[];
    const int tid = threadIdx.x;
    const int lane = tid & 31;
    const int wid = tid >> 5;        // 0..15
    const int wm = wid >> 1;         // 0..7  (32-row band)
    const int wn = wid & 1;          // 0..1  (64-col band)
    const int grp = lane >> 2;
    const int tig = lane & 3;

    const int nt = blockIdx.x;       // 0..31
    const int mt = blockIdx.y;       // 0..63
    const uint32_t sb = smem_u32(smem4);

    const uint4* Abase = g_A + (size_t)mt * NKT * A_TILE_U4;
    const uint4* Wbase = g_W + (size_t)nt * NKT * W_TILE_U4;

    #define LOAD_STAGE(slot, kt)                                               \
    {                                                                          \
        uint32_t s0 = sb + (uint32_t)(slot) * STAGE_BYTES;                     \
        const uint4* ag = Abase + (size_t)(kt) * A_TILE_U4;                    \
        _Pragma("unroll")                                                      \
        for (int c = 0; c < 6; c++) {                                          \
            int id = tid + c * NTHREADS;                                       \
            cp16(s0 + (uint32_t)id * 16, ag + id);                             \
        }                                                                      \
        const uint4* wg = Wbase + (size_t)(kt) * W_TILE_U4;                    \
        uint32_t s1 = s0 + A_TILE_U4 * 16;                                     \
        _Pragma("unroll")                                                      \
        for (int c = 0; c < 3; c++) {                                          \
            int id = tid + c * NTHREADS;                                       \
            cp16(s1 + (uint32_t)id * 16, wg + id);                             \
        }                                                                      \
    }

    float acc[2][8][4];
    #pragma unroll
    for (int i = 0; i < 2; i++)
        #pragma unroll
        for (int j = 0; j < 8; j++)
            #pragma unroll
            for (int q = 0; q < 4; q++) acc[i][j][q] = 0.0f;

    LOAD_STAGE(0, 0) CP_COMMIT();
    LOAD_STAGE(1, 1) CP_COMMIT();

    for (int kt = 0; kt < NKT; kt++) {
        const int slot = kt % NSTAGES;
        CP_WAIT1();                       // stage kt complete (kt+1 may fly)
        __syncthreads();                  // everyone done with slot being refilled
        if (kt + 2 < NKT) {
            LOAD_STAGE((kt + 2) % NSTAGES, kt + 2)
        }
        CP_COMMIT();

        const uint4* S   = smem4 + slot * STAGE_U4;
        const uint4* Afp = S;             // [mb16][kb2][lane]
        const uint4* Abf = S + 1024;      // [mb16][kb4][lane]
        const uint4* Wfp = S + A_TILE_U4;         // [nbp8][kb2][lane]
        const uint4* Wbf = S + A_TILE_U4 + 512;   // [nbp8][kb4][lane]

        // fp16 hi*hi : 2 k16 slices
        #pragma unroll
        for (int s = 0; s < 2; s++) {
            uint4 a0 = Afp[((wm * 2) * 2 + s) * 32 + lane];
            uint4 a1 = Afp[((wm * 2 + 1) * 2 + s) * 32 + lane];
            #pragma unroll
            for (int p = 0; p < 4; p++) {
                uint4 w = Wfp[((wn * 4 + p) * 2 + s) * 32 + lane];
                mma_f16(acc[0][2 * p],     a0, w.x, w.y);
                mma_f16(acc[0][2 * p + 1], a0, w.z, w.w);
                mma_f16(acc[1][2 * p],     a1, w.x, w.y);
                mma_f16(acc[1][2 * p + 1], a1, w.z, w.w);
            }
        }
        // bf16 crosses: j0,1 = lo_a*w ; j2,3 = a*lo_w
        #pragma unroll
        for (int j = 0; j < 4; j++) {
            uint4 ab0 = Abf[((wm * 2) * 4 + j) * 32 + lane];
            uint4 ab1 = Abf[((wm * 2 + 1) * 4 + j) * 32 + lane];
            #pragma unroll
            for (int p = 0; p < 4; p++) {
                uint4 wb = Wbf[((wn * 4 + p) * 4 + j) * 32 + lane];
                mma_bf16(acc[0][2 * p],     ab0, wb.x, wb.y);
                mma_bf16(acc[0][2 * p + 1], ab0, wb.z, wb.w);
                mma_bf16(acc[1][2 * p],     ab1, wb.x, wb.y);
                mma_bf16(acc[1][2 * p + 1], ab1, wb.z, wb.w);
            }
        }
    }

    // ---- epilogue ----
    const float OFF = -235.24826450039622f - 8.317766166719343f;
    const int m0 = mt * BM, n0 = nt * BN;
    #pragma unroll
    for (int ml = 0; ml < 2; ml++) {
        #pragma unroll
        for (int ntl = 0; ntl < 8; ntl++) {
            int row = m0 + wm * 32 + ml * 16 + grp;
            int col = n0 + wn * 64 + ntl * 8 + tig * 2;
            float c0 = __ldg(g_constc + col);
            float c1 = __ldg(g_constc + col + 1);
            float2 o0, o1;
            o0.x = fmaf(-0.5f, acc[ml][ntl][0] + c0, OFF);
            o0.y = fmaf(-0.5f, acc[ml][ntl][1] + c1, OFF);
            o1.x = fmaf(-0.5f, acc[ml][ntl][2] + c0, OFF);
            o1.y = fmaf(-0.5f, acc[ml][ntl][3] + c1, OFF);
            *(float2*)(out + (size_t)row * C_SZ + col)       = o0;
            *(float2*)(out + (size_t)(row + 8) * C_SZ + col) = o1;
        }
    }
}

// ---------------- softmax / argmax (smem row cache) ----------------
__global__ void __launch_bounds__(256)
softmax_rows_kernel(const float* __restrict__ logits,
                    float* __restrict__ probs,
                    float* __restrict__ pred) {
    const int b = blockIdx.x, tid = threadIdx.x;
    __shared__ float row[C_SZ];
    __shared__ float sm[256]; __shared__ int si[256]; __shared__ float ss[256];

    const float4* src = (const float4*)(logits + (size_t)b * C_SZ);
    #pragma unroll
    for (int i = tid; i < C_SZ / 4; i += 256) ((float4*)row)[i] = src[i];
    __syncthreads();

    float m = -INFINITY; int mi = 0;
    #pragma unroll
    for (int k = 0; k < C_SZ / 256; k++) {
        int c = k * 256 + tid;
        float v = row[c];
        if (v > m) { m = v; mi = c; }
    }
    sm[tid] = m; si[tid] = mi;
    __syncthreads();
    #pragma unroll
    for (int s = 128; s > 0; s >>= 1) {
        if (tid < s) {
            if (sm[tid + s] > sm[tid] ||
                (sm[tid + s] == sm[tid] && si[tid + s] < si[tid])) {
                sm[tid] = sm[tid + s]; si[tid] = si[tid + s];
            }
        }
        __syncthreads();
    }
    const float rmax = sm[0];
    const int amax = si[0];

    float s = 0.0f;
    #pragma unroll
    for (int k = 0; k < C_SZ / 256; k++) s += __expf(row[k * 256 + tid] - rmax);
    ss[tid] = s;
    __syncthreads();
    #pragma unroll
    for (int st = 128; st > 0; st >>= 1) {
        if (tid < st) ss[tid] += ss[tid + st];
        __syncthreads();
    }
    const float inv = 1.0f / ss[0];

    float* dst = probs + (size_t)b * C_SZ;
    #pragma unroll
    for (int k = 0; k < C_SZ / 256; k++) {
        int c = k * 256 + tid;
        dst[c] = __expf(row[c] - rmax) * inv;
    }
    if (tid == 0) pred[b] = (float)amax;
}

// ---------------- launch ----------------
extern "C" void kernel_launch(void* const* d_in, const int* in_sizes, int n_in,
                              void* d_out, int out_size) {
    const float* z      = (const float*)d_in[0];
    const float* mu     = (const float*)d_in[1];
    const float* logvar = (const float*)d_in[2];
    float* out = (float*)d_out;

    float* logits = out;
    float* probs  = out + (size_t)B_SZ * C_SZ;
    float* pred   = out + (size_t)2 * B_SZ * C_SZ;

    cudaFuncSetAttribute(gemm_hybrid_kernel,
                         cudaFuncAttributeMaxDynamicSharedMemorySize, SMEM_BYTES);

    prep_Afp_kernel<<<1048576 / 256, 256>>>(z);
    prep_Abf_kernel<<<2097152 / 256, 256>>>(z);
    prep_Wfp_kernel<<<262144 / 256, 256>>>(mu, logvar);
    prep_Wbf_kernel<<<524288 / 256, 256>>>(mu, logvar);
    prep_const_kernel<<<C_SZ, 256>>>(mu, logvar);

    dim3 grid(C_SZ / BN, B_SZ / BM);       // (32, 64)
    gemm_hybrid_kernel<<<grid, NTHREADS, SMEM_BYTES>>>(logits);

    softmax_rows_kernel<<<B_SZ, 256>>>(logits, probs, pred);
}

// round 8
// speedup vs baseline: 2.9727x; 1.1007x over previous
#include <cuda_runtime.h>
#include <cuda_bf16.h>
#include <cuda_fp16.h>
#include <cstdint>
#include <math.h>

// ---------------- problem shape ----------------
#define B_SZ 16384
#define C_SZ 4096
#define D_SZ 256
// logical K = 512 : A = [z^2 | z],  W = [iv | -2*mu*iv]

// ---------------- GEMM tile ----------------
#define BM 256
#define BN 128
#define NKT 16             // k-tiles of 32
#define NTHREADS 256       // 8 warps, each owns a 64x64 output tile

// tile images (uint4 units):
//  A tile: [fp16 hi: mb16 x ks2 x lane32 = 1024 | bf16: mb16 x kb4 x lane32 = 2048] = 3072
//  W tile: [fp16 hi: nbp8 x ks2 x lane32 = 512  | bf16: nbp8 x kb4 x lane32 = 1024] = 1536
#define A_TILE_U4 3072
#define W_TILE_U4 1536
#define STAGE_U4 (A_TILE_U4 + W_TILE_U4)            // 4608 -> 72KB
#define STAGE_BYTES (STAGE_U4 * 16)
#define NSTAGES 3
#define SMEM_BYTES (NSTAGES * STAGE_BYTES)          // 221184

// -------- scratch (__device__ globals; no allocation allowed) --------
__device__ uint4 g_A[(size_t)64 * NKT * A_TILE_U4];   // 48 MB
__device__ uint4 g_W[(size_t)32 * NKT * W_TILE_U4];   // 12 MB
__device__ float g_constc[C_SZ];

// ---------------- helpers ----------------
#define FP16_MIN_NORMAL 6.104e-5f

__device__ __forceinline__ float fp16_hi(float x) {
    if (fabsf(x) < FP16_MIN_NORMAL) return 0.0f;     // keep hi a NORMAL fp16 (or 0)
    return __half2float(__float2half_rn(x));
}
__device__ __forceinline__ uint32_t pack_h2(float e, float o) {
    __half2 t;
    t.x = (fabsf(e) < FP16_MIN_NORMAL) ? __half(0.0f) : __float2half_rn(e);
    t.y = (fabsf(o) < FP16_MIN_NORMAL) ? __half(0.0f) : __float2half_rn(o);
    return *(uint32_t*)&t;
}
__device__ __forceinline__ uint32_t pack_bf16(float e, float o) {
    __nv_bfloat162 t = __floats2bfloat162_rn(e, o);
    return *(uint32_t*)&t;
}
__device__ __forceinline__ uint32_t smem_u32(const void* p) {
    uint32_t a;
    asm("{ .reg .u64 t; cvta.to.shared.u64 t, %1; cvt.u32.u64 %0, t; }" : "=r"(a) : "l"(p));
    return a;
}
__device__ __forceinline__ void cp16(uint32_t dst, const void* src) {
    asm volatile("cp.async.cg.shared.global [%0], [%1], 16;" :: "r"(dst), "l"(src));
}
#define CP_COMMIT() asm volatile("cp.async.commit_group;" ::: "memory")
#define CP_WAIT1()  asm volatile("cp.async.wait_group 1;" ::: "memory")

__device__ __forceinline__ void mma_f16(float* d, const uint4& a, uint32_t b0, uint32_t b1) {
    asm volatile(
        "mma.sync.aligned.m16n8k16.row.col.f32.f16.f16.f32 "
        "{%0,%1,%2,%3}, {%4,%5,%6,%7}, {%8,%9}, {%0,%1,%2,%3};"
        : "+f"(d[0]), "+f"(d[1]), "+f"(d[2]), "+f"(d[3])
        : "r"(a.x), "r"(a.y), "r"(a.z), "r"(a.w), "r"(b0), "r"(b1));
}
__device__ __forceinline__ void mma_bf16(float* d, const uint4& a, uint32_t b0, uint32_t b1) {
    asm volatile(
        "mma.sync.aligned.m16n8k16.row.col.f32.bf16.bf16.f32 "
        "{%0,%1,%2,%3}, {%4,%5,%6,%7}, {%8,%9}, {%0,%1,%2,%3};"
        : "+f"(d[0]), "+f"(d[1]), "+f"(d[2]), "+f"(d[3])
        : "r"(a.x), "r"(a.y), "r"(a.z), "r"(a.w), "r"(b0), "r"(b1));
}

// logical operand values
__device__ __forceinline__ float Aval(const float* __restrict__ z, int r, int k) {
    float v = __ldg(z + (size_t)r * D_SZ + (k & 255));
    return (k < 256) ? v * v : v;
}
__device__ __forceinline__ float Wval(const float* __restrict__ mu,
                                      const float* __restrict__ lv, int c, int k) {
    int d = k & 255;
    float l = __ldg(lv + (size_t)c * D_SZ + d);
    float iv = expf(-l);
    return (k < 256) ? iv : -2.0f * __ldg(mu + (size_t)c * D_SZ + d) * iv;
}

// ---------------- merged prep kernels ----------------
// A: one thread per (mt, kt, mb, ks, lane) writes fp16-hi u4 + bf16-lo u4 + bf16-full u4
// fields: lane[0:5) ks[5:6) mb[6:10) kt[10:14) mt[14:)
__global__ void prep_A_kernel(const float* __restrict__ z) {
    int idx = blockIdx.x * blockDim.x + threadIdx.x;   // 1,048,576
    int lane = idx & 31, ks = (idx >> 5) & 1, mb = (idx >> 6) & 15;
    int kt = (idx >> 10) & 15, mt = idx >> 14;
    int grp = lane >> 2, tig = lane & 3;
    int r0 = mt * 256 + mb * 16 + grp;
    int kbase = kt * 32 + ks * 16;
    int ke0 = kbase + tig * 2, ke1 = kbase + 8 + tig * 2;

    float a00 = Aval(z, r0, ke0),     a01 = Aval(z, r0, ke0 + 1);
    float a10 = Aval(z, r0 + 8, ke0), a11 = Aval(z, r0 + 8, ke0 + 1);
    float a20 = Aval(z, r0, ke1),     a21 = Aval(z, r0, ke1 + 1);
    float a30 = Aval(z, r0 + 8, ke1), a31 = Aval(z, r0 + 8, ke1 + 1);

    uint4 hi, lo, fl;
    hi.x = pack_h2(a00, a01); hi.y = pack_h2(a10, a11);
    hi.z = pack_h2(a20, a21); hi.w = pack_h2(a30, a31);
    lo.x = pack_bf16(a00 - fp16_hi(a00), a01 - fp16_hi(a01));
    lo.y = pack_bf16(a10 - fp16_hi(a10), a11 - fp16_hi(a11));
    lo.z = pack_bf16(a20 - fp16_hi(a20), a21 - fp16_hi(a21));
    lo.w = pack_bf16(a30 - fp16_hi(a30), a31 - fp16_hi(a31));
    fl.x = pack_bf16(a00, a01); fl.y = pack_bf16(a10, a11);
    fl.z = pack_bf16(a20, a21); fl.w = pack_bf16(a30, a31);

    size_t base = (size_t)(mt * NKT + kt) * A_TILE_U4;
    g_A[base + (mb * 2 + ks) * 32 + lane] = hi;
    g_A[base + 1024 + (mb * 4 + ks) * 32 + lane] = lo;        // kb<2 : lo_a
    g_A[base + 1024 + (mb * 4 + 2 + ks) * 32 + lane] = fl;    // kb>=2: full a
}

// W: one thread per (nt, kt, nbp, ks, lane) writes fp16-hi u4 + bf16-full u4 + bf16-lo u4
// fields: lane[0:5) ks[5:6) nbp[6:9) kt[9:13) nt[13:)
__global__ void prep_W_kernel(const float* __restrict__ mu,
                              const float* __restrict__ logvar) {
    int idx = blockIdx.x * blockDim.x + threadIdx.x;   // 262,144
    int lane = idx & 31, ks = (idx >> 5) & 1, nbp = (idx >> 6) & 7;
    int kt = (idx >> 9) & 15, nt = idx >> 13;
    int grp = lane >> 2, tig = lane & 3;
    int c0 = nt * 128 + nbp * 16 + grp;
    int c1 = c0 + 8;
    int kbase = kt * 32 + ks * 16;
    int ke0 = kbase + tig * 2, ke1 = kbase + 8 + tig * 2;

    float w00 = Wval(mu, logvar, c0, ke0), w01 = Wval(mu, logvar, c0, ke0 + 1);
    float w10 = Wval(mu, logvar, c0, ke1), w11 = Wval(mu, logvar, c0, ke1 + 1);
    float w20 = Wval(mu, logvar, c1, ke0), w21 = Wval(mu, logvar, c1, ke0 + 1);
    float w30 = Wval(mu, logvar, c1, ke1), w31 = Wval(mu, logvar, c1, ke1 + 1);

    uint4 hi, fl, lo;
    hi.x = pack_h2(w00, w01); hi.y = pack_h2(w10, w11);
    hi.z = pack_h2(w20, w21); hi.w = pack_h2(w30, w31);
    fl.x = pack_bf16(w00, w01); fl.y = pack_bf16(w10, w11);
    fl.z = pack_bf16(w20, w21); fl.w = pack_bf16(w30, w31);
    lo.x = pack_bf16(w00 - fp16_hi(w00), w01 - fp16_hi(w01));
    lo.y = pack_bf16(w10 - fp16_hi(w10), w11 - fp16_hi(w11));
    lo.z = pack_bf16(w20 - fp16_hi(w20), w21 - fp16_hi(w21));
    lo.w = pack_bf16(w30 - fp16_hi(w30), w31 - fp16_hi(w31));

    size_t base = (size_t)(nt * NKT + kt) * W_TILE_U4;
    g_W[base + (nbp * 2 + ks) * 32 + lane] = hi;
    g_W[base + 512 + (nbp * 4 + ks) * 32 + lane] = fl;        // kb<2 : full w
    g_W[base + 512 + (nbp * 4 + 2 + ks) * 32 + lane] = lo;    // kb>=2: lo_w
}

__global__ void prep_const_kernel(const float* __restrict__ mu,
                                  const float* __restrict__ logvar) {
    int c = blockIdx.x, d = threadIdx.x;
    float lv = logvar[(size_t)c * D_SZ + d];
    float m  = mu[(size_t)c * D_SZ + d];
    float iv = expf(-lv);
    __shared__ float red[256];
    red[d] = fmaf(m * m, iv, lv);
    __syncthreads();
    #pragma unroll
    for (int s = 128; s > 0; s >>= 1) {
        if (d < s) red[d] += red[d + s];
        __syncthreads();
    }
    if (d == 0) g_constc[c] = red[0];
}

// ---------------- GEMM: 8 warps x (64x64) warp tiles ----------------
__global__ void __launch_bounds__(NTHREADS, 1)
gemm_hybrid_kernel(float* __restrict__ out) {
    extern __shared__ uint4 smem4[];
    const int tid = threadIdx.x;
    const int lane = tid & 31;
    const int wid = tid >> 5;        // 0..7
    const int wm = wid >> 1;         // 0..3  (64-row band)
    const int wn = wid & 1;          // 0..1  (64-col band)
    const int grp = lane >> 2;
    const int tig = lane & 3;

    const int nt = blockIdx.x;       // 0..31
    const int mt = blockIdx.y;       // 0..63
    const uint32_t sb = smem_u32(smem4);

    const uint4* Abase = g_A + (size_t)mt * NKT * A_TILE_U4;
    const uint4* Wbase = g_W + (size_t)nt * NKT * W_TILE_U4;

    #define LOAD_STAGE(slot, kt)                                               \
    {                                                                          \
        uint32_t s0 = sb + (uint32_t)(slot) * STAGE_BYTES;                     \
        const uint4* ag = Abase + (size_t)(kt) * A_TILE_U4;                    \
        _Pragma("unroll")                                                      \
        for (int c = 0; c < 12; c++) {                                         \
            int id = tid + c * NTHREADS;                                       \
            cp16(s0 + (uint32_t)id * 16, ag + id);                             \
        }                                                                      \
        const uint4* wg = Wbase + (size_t)(kt) * W_TILE_U4;                    \
        uint32_t s1 = s0 + A_TILE_U4 * 16;                                     \
        _Pragma("unroll")                                                      \
        for (int c = 0; c < 6; c++) {                                          \
            int id = tid + c * NTHREADS;                                       \
            cp16(s1 + (uint32_t)id * 16, wg + id);                             \
        }                                                                      \
    }

    float acc[4][8][4];              // [m-frag][n8 group][4]
    #pragma unroll
    for (int i = 0; i < 4; i++)
        #pragma unroll
        for (int j = 0; j < 8; j++)
            #pragma unroll
            for (int q = 0; q < 4; q++) acc[i][j][q] = 0.0f;

    LOAD_STAGE(0, 0) CP_COMMIT();
    LOAD_STAGE(1, 1) CP_COMMIT();

    for (int kt = 0; kt < NKT; kt++) {
        const int slot = kt % NSTAGES;
        CP_WAIT1();
        __syncthreads();
        if (kt + 2 < NKT) {
            LOAD_STAGE((kt + 2) % NSTAGES, kt + 2)
        }
        CP_COMMIT();

        const uint4* S   = smem4 + slot * STAGE_U4;
        const uint4* Afp = S;                     // [mb16][ks2][lane]
        const uint4* Abf = S + 1024;              // [mb16][kb4][lane]
        const uint4* Wfp = S + A_TILE_U4;         // [nbp8][ks2][lane]
        const uint4* Wbf = S + A_TILE_U4 + 512;   // [nbp8][kb4][lane]

        // fp16 hi*hi : 2 k16 slices
        #pragma unroll
        for (int s = 0; s < 2; s++) {
            uint4 a[4], w[4];
            #pragma unroll
            for (int mf = 0; mf < 4; mf++)
                a[mf] = Afp[((wm * 4 + mf) * 2 + s) * 32 + lane];
            #pragma unroll
            for (int p = 0; p < 4; p++)
                w[p] = Wfp[((wn * 4 + p) * 2 + s) * 32 + lane];
            #pragma unroll
            for (int mf = 0; mf < 4; mf++)
                #pragma unroll
                for (int p = 0; p < 4; p++) {
                    mma_f16(acc[mf][2 * p],     a[mf], w[p].x, w[p].y);
                    mma_f16(acc[mf][2 * p + 1], a[mf], w[p].z, w[p].w);
                }
        }
        // bf16 crosses: j0,1 = lo_a*w ; j2,3 = a*lo_w
        #pragma unroll
        for (int j = 0; j < 4; j++) {
            uint4 a[4], w[4];
            #pragma unroll
            for (int mf = 0; mf < 4; mf++)
                a[mf] = Abf[((wm * 4 + mf) * 4 + j) * 32 + lane];
            #pragma unroll
            for (int p = 0; p < 4; p++)
                w[p] = Wbf[((wn * 4 + p) * 4 + j) * 32 + lane];
            #pragma unroll
            for (int mf = 0; mf < 4; mf++)
                #pragma unroll
                for (int p = 0; p < 4; p++) {
                    mma_bf16(acc[mf][2 * p],     a[mf], w[p].x, w[p].y);
                    mma_bf16(acc[mf][2 * p + 1], a[mf], w[p].z, w[p].w);
                }
        }
    }

    // ---- epilogue ----
    const float OFF = -235.24826450039622f - 8.317766166719343f;
    const int m0 = mt * BM, n0 = nt * BN;
    #pragma unroll
    for (int mf = 0; mf < 4; mf++) {
        #pragma unroll
        for (int g = 0; g < 8; g++) {
            int row = m0 + wm * 64 + mf * 16 + grp;
            int col = n0 + wn * 64 + g * 8 + tig * 2;
            float c0 = __ldg(g_constc + col);
            float c1 = __ldg(g_constc + col + 1);
            float2 o0, o1;
            o0.x = fmaf(-0.5f, acc[mf][g][0] + c0, OFF);
            o0.y = fmaf(-0.5f, acc[mf][g][1] + c1, OFF);
            o1.x = fmaf(-0.5f, acc[mf][g][2] + c0, OFF);
            o1.y = fmaf(-0.5f, acc[mf][g][3] + c1, OFF);
            *(float2*)(out + (size_t)row * C_SZ + col)       = o0;
            *(float2*)(out + (size_t)(row + 8) * C_SZ + col) = o1;
        }
    }
}

// ---------------- softmax / argmax (smem row cache) ----------------
__global__ void __launch_bounds__(256)
softmax_rows_kernel(const float* __restrict__ logits,
                    float* __restrict__ probs,
                    float* __restrict__ pred) {
    const int b = blockIdx.x, tid = threadIdx.x;
    __shared__ float row[C_SZ];
    __shared__ float sm[256]; __shared__ int si[256]; __shared__ float ss[256];

    const float4* src = (const float4*)(logits + (size_t)b * C_SZ);
    #pragma unroll
    for (int i = tid; i < C_SZ / 4; i += 256) ((float4*)row)[i] = src[i];
    __syncthreads();

    float m = -INFINITY; int mi = 0;
    #pragma unroll
    for (int k = 0; k < C_SZ / 256; k++) {
        int c = k * 256 + tid;
        float v = row[c];
        if (v > m) { m = v; mi = c; }
    }
    sm[tid] = m; si[tid] = mi;
    __syncthreads();
    #pragma unroll
    for (int s = 128; s > 0; s >>= 1) {
        if (tid < s) {
            if (sm[tid + s] > sm[tid] ||
                (sm[tid + s] == sm[tid] && si[tid + s] < si[tid])) {
                sm[tid] = sm[tid + s]; si[tid] = si[tid + s];
            }
        }
        __syncthreads();
    }
    const float rmax = sm[0];
    const int amax = si[0];

    float s = 0.0f;
    #pragma unroll
    for (int k = 0; k < C_SZ / 256; k++) s += __expf(row[k * 256 + tid] - rmax);
    ss[tid] = s;
    __syncthreads();
    #pragma unroll
    for (int st = 128; st > 0; st >>= 1) {
        if (tid < st) ss[tid] += ss[tid + st];
        __syncthreads();
    }
    const float inv = 1.0f / ss[0];

    float* dst = probs + (size_t)b * C_SZ;
    #pragma unroll
    for (int k = 0; k < C_SZ / 256; k++) {
        int c = k * 256 + tid;
        dst[c] = __expf(row[c] - rmax) * inv;
    }
    if (tid == 0) pred[b] = (float)amax;
}

// ---------------- launch ----------------
extern "C" void kernel_launch(void* const* d_in, const int* in_sizes, int n_in,
                              void* d_out, int out_size) {
    const float* z      = (const float*)d_in[0];
    const float* mu     = (const float*)d_in[1];
    const float* logvar = (const float*)d_in[2];
    float* out = (float*)d_out;

    float* logits = out;
    float* probs  = out + (size_t)B_SZ * C_SZ;
    float* pred   = out + (size_t)2 * B_SZ * C_SZ;

    cudaFuncSetAttribute(gemm_hybrid_kernel,
                         cudaFuncAttributeMaxDynamicSharedMemorySize, SMEM_BYTES);

    prep_A_kernel<<<1048576 / 256, 256>>>(z);
    prep_W_kernel<<<262144 / 256, 256>>>(mu, logvar);
    prep_const_kernel<<<C_SZ, 256>>>(mu, logvar);

    dim3 grid(C_SZ / BN, B_SZ / BM);       // (32, 64)
    gemm_hybrid_kernel<<<grid, NTHREADS, SMEM_BYTES>>>(logits);

    softmax_rows_kernel<<<B_SZ, 256>>>(logits, probs, pred);
}